// round 9
// baseline (speedup 1.0000x reference)
#include <cuda_runtime.h>
#include <cuda_bf16.h>
#include <math.h>
#include <stdint.h>

#define BATCH 32
#define DIM   384
#define NTOK  1024
#define STAGES 3

typedef __nv_bfloat16 bf16;

// ---------------------------------------------------------------------------
// Scratch (allocation-free rule: __device__ globals). All operands pre-split
// into hi/lo bf16 pairs; S kept in f32 for softmax precision.
// ---------------------------------------------------------------------------
#define ND ((size_t)BATCH * NTOK * DIM)
#define NN ((size_t)BATCH * NTOK * NTOK)
#define WW ((size_t)DIM * DIM)

__device__ bf16 g_t1h[ND], g_t1l[ND];   // rgb^T [n][c]
__device__ bf16 g_t2h[ND], g_t2l[ND];   // ms^T  [n][c]
__device__ bf16 g_qh[ND],  g_ql[ND];    // qT [n][d]
__device__ bf16 g_kh[ND],  g_kl[ND];    // kT [n][d]
__device__ bf16 g_vh[ND],  g_vl[ND];    // v  [d][n]
__device__ bf16 g_oh[ND],  g_ol[ND];    // oT [n][d]
__device__ bf16 g_Ph[NN],  g_Pl[NN];    // attn [i][m]
__device__ float g_s[NN];               // scores f32
__device__ bf16 g_wh[4 * WW], g_wl[4 * WW]; // Wq,Wk,Wv,Wf split

// ---------------------------------------------------------------------------
// helpers
// ---------------------------------------------------------------------------
__device__ __forceinline__ void split1(float x, bf16& h, bf16& l) {
    h = __float2bfloat16(x);
    l = __float2bfloat16(x - __bfloat162float(h));
}

__device__ __forceinline__ void cpasync16(uint32_t dst, const void* src) {
    asm volatile("cp.async.cg.shared.global [%0], [%1], 16;" :: "r"(dst), "l"(src));
}

__device__ __forceinline__ void ldmA(uint32_t f[4], const uint32_t* base, int rb, int lane) {
    int t = lane >> 3, rr = lane & 7;
    int row = rb + rr + (t & 1) * 8;
    int c = ((t >> 1) << 2) ^ (row & 4);
    uint32_t sa = (uint32_t)__cvta_generic_to_shared(&base[row * 8 + c]);
    asm volatile("ldmatrix.sync.aligned.m8n8.x4.shared.b16 {%0,%1,%2,%3}, [%4];"
                 : "=r"(f[0]), "=r"(f[1]), "=r"(f[2]), "=r"(f[3]) : "r"(sa));
}

__device__ __forceinline__ void ldmB(uint32_t f[2], const uint32_t* base, int cb, int lane) {
    int row = cb + (lane & 7);
    int c = (((lane >> 3) & 1) << 2) ^ (row & 4);
    uint32_t sa = (uint32_t)__cvta_generic_to_shared(&base[row * 8 + c]);
    asm volatile("ldmatrix.sync.aligned.m8n8.x2.shared.b16 {%0,%1}, [%2];"
                 : "=r"(f[0]), "=r"(f[1]) : "r"(sa));
}

__device__ __forceinline__ void mma(float acc[4], const uint32_t a[4], const uint32_t b[2]) {
    asm volatile("mma.sync.aligned.m16n8k16.row.col.f32.bf16.bf16.f32 "
                 "{%0,%1,%2,%3}, {%4,%5,%6,%7}, {%8,%9}, {%0,%1,%2,%3};"
                 : "+f"(acc[0]), "+f"(acc[1]), "+f"(acc[2]), "+f"(acc[3])
                 : "r"(a[0]), "r"(a[1]), "r"(a[2]), "r"(a[3]), "r"(b[0]), "r"(b[1]));
}

// Stage layout (dynamic smem):
//   stage (32KB) = [sub(2)][tile(4: Ah,Al,Bh,Bl)][128 rows x 8 u32 swizzled]
#define TILE_U32   1024u                 // 4KB per tile
#define SUB_U32    (4u * TILE_U32)       // 16KB per sub-chunk
#define STAGE_U32  (2u * SUB_U32)        // 32KB per stage
#define SMEM_BYTES (STAGES * STAGE_U32 * 4u)  // 96KB

// ---------------------------------------------------------------------------
// Universal NT GEMM over pre-split bf16 operands, cp.async pipeline, TK=32.
// C[b][m][n] = scale * sum_k (Ah+Al)[b][m][k] * (Bh+Bl)[b][n][k]  (+ bias)
// OUT: 0 -> f32 Cf   1 -> split bf16 (Ch, Cl)
// BM : 0 none, 1 row-bias bias[m], 2 col-bias bias[n]
// CTA 128x128, 256 threads, 2 CTAs/SM. K % 32 == 0.
// ---------------------------------------------------------------------------
template<int OUT, int BM>
__global__ __launch_bounds__(256, 2) void k_gemm(
    const bf16* __restrict__ Ah, const bf16* __restrict__ Al,
    const bf16* __restrict__ Bh, const bf16* __restrict__ Bl,
    const float* __restrict__ bias,
    float* __restrict__ Cf, bf16* __restrict__ Ch, bf16* __restrict__ Cl,
    int M, int N, int K, size_t strA, size_t strB, size_t strC, float scale)
{
    extern __shared__ uint32_t sm[];

    const int tid = threadIdx.x, lane = tid & 31, wid = tid >> 5;
    const int wm = wid >> 2, wn = wid & 3, g = lane >> 2, q = lane & 3;
    const int m0 = blockIdx.y * 128, n0 = blockIdx.x * 128;
    const size_t zb = blockIdx.z;

    const int r = tid >> 1, h = tid & 1;
    const bf16* pAh = Ah + zb * strA + (size_t)(m0 + r) * K + 8 * h;
    const bf16* pAl = Al + zb * strA + (size_t)(m0 + r) * K + 8 * h;
    const bf16* pBh = Bh + zb * strB + (size_t)(n0 + r) * K + 8 * h;
    const bf16* pBl = Bl + zb * strB + (size_t)(n0 + r) * K + 8 * h;
    const uint32_t dOff = (uint32_t)((r * 8 + ((4 * h) ^ (r & 4))) * 4);
    const uint32_t smBase = (uint32_t)__cvta_generic_to_shared(sm);

    const int nIt = K >> 5;   // TK = 32

    auto issue = [&](int s) {
        if (s < nIt) {
            const uint32_t stg = smBase + (uint32_t)(s % STAGES) * (STAGE_U32 * 4u);
#pragma unroll
            for (int sub = 0; sub < 2; sub++) {
                const size_t ko = (size_t)s * 32 + sub * 16;
                const uint32_t sbase = stg + (uint32_t)sub * (SUB_U32 * 4u) + dOff;
                cpasync16(sbase + 0 * (TILE_U32 * 4u), pAh + ko);
                cpasync16(sbase + 1 * (TILE_U32 * 4u), pAl + ko);
                cpasync16(sbase + 2 * (TILE_U32 * 4u), pBh + ko);
                cpasync16(sbase + 3 * (TILE_U32 * 4u), pBl + ko);
            }
        }
        asm volatile("cp.async.commit_group;");
    };

    float acc[4][4][4] = {};

    issue(0);
    issue(1);

    for (int it = 0; it < nIt; it++) {
        asm volatile("cp.async.wait_group 1;");
        __syncthreads();
        issue(it + 2);

        const uint32_t* stg = sm + (uint32_t)(it % STAGES) * STAGE_U32;

#pragma unroll
        for (int sub = 0; sub < 2; sub++) {
            const uint32_t* SAh = stg + sub * SUB_U32;
            const uint32_t* SAl = SAh + TILE_U32;
            const uint32_t* SBh = SAh + 2 * TILE_U32;
            const uint32_t* SBl = SAh + 3 * TILE_U32;

            uint32_t bh[4][2], bl[4][2];
#pragma unroll
            for (int nt = 0; nt < 4; nt++) {
                ldmB(bh[nt], SBh, wn * 32 + nt * 8, lane);
                ldmB(bl[nt], SBl, wn * 32 + nt * 8, lane);
            }

#pragma unroll
            for (int mh = 0; mh < 2; mh++) {
                uint32_t ah[2][4], al[2][4];
#pragma unroll
                for (int m2 = 0; m2 < 2; m2++) {
                    ldmA(ah[m2], SAh, wm * 64 + (mh * 2 + m2) * 16, lane);
                    ldmA(al[m2], SAl, wm * 64 + (mh * 2 + m2) * 16, lane);
                }
#pragma unroll
                for (int m2 = 0; m2 < 2; m2++)
#pragma unroll
                    for (int nt = 0; nt < 4; nt++)
                        mma(acc[mh * 2 + m2][nt], ah[m2], bl[nt]);
#pragma unroll
                for (int m2 = 0; m2 < 2; m2++)
#pragma unroll
                    for (int nt = 0; nt < 4; nt++)
                        mma(acc[mh * 2 + m2][nt], al[m2], bh[nt]);
#pragma unroll
                for (int m2 = 0; m2 < 2; m2++)
#pragma unroll
                    for (int nt = 0; nt < 4; nt++)
                        mma(acc[mh * 2 + m2][nt], ah[m2], bh[nt]);
            }
        }
    }

    // epilogue
    float* Cfb = (OUT == 0) ? Cf + zb * strC : nullptr;
    bf16* Chb = (OUT == 1) ? Ch + zb * strC : nullptr;
    bf16* Clb = (OUT == 1) ? Cl + zb * strC : nullptr;

#pragma unroll
    for (int mt = 0; mt < 4; mt++) {
        const int rr = m0 + wm * 64 + mt * 16 + g;
        float br0 = 0.f, br1 = 0.f;
        if (BM == 1) { br0 = bias[rr]; br1 = bias[rr + 8]; }
#pragma unroll
        for (int nt = 0; nt < 4; nt++) {
            const int cc = n0 + wn * 32 + nt * 8 + 2 * q;
            float v0 = acc[mt][nt][0] * scale, v1 = acc[mt][nt][1] * scale;
            float v2 = acc[mt][nt][2] * scale, v3 = acc[mt][nt][3] * scale;
            if (BM == 1) { v0 += br0; v1 += br0; v2 += br1; v3 += br1; }
            if (BM == 2) {
                float bc0 = bias[cc], bc1 = bias[cc + 1];
                v0 += bc0; v1 += bc1; v2 += bc0; v3 += bc1;
            }
            if (OUT == 0) {
                *reinterpret_cast<float2*>(&Cfb[(size_t)rr * N + cc]) = make_float2(v0, v1);
                *reinterpret_cast<float2*>(&Cfb[(size_t)(rr + 8) * N + cc]) = make_float2(v2, v3);
            } else {
                bf16 h0, l0, h1, l1, h2, l2, h3, l3;
                split1(v0, h0, l0); split1(v1, h1, l1);
                split1(v2, h2, l2); split1(v3, h3, l3);
                *reinterpret_cast<__nv_bfloat162*>(&Chb[(size_t)rr * N + cc]) =
                    __nv_bfloat162(h0, h1);
                *reinterpret_cast<__nv_bfloat162*>(&Clb[(size_t)rr * N + cc]) =
                    __nv_bfloat162(l0, l1);
                *reinterpret_cast<__nv_bfloat162*>(&Chb[(size_t)(rr + 8) * N + cc]) =
                    __nv_bfloat162(h2, h3);
                *reinterpret_cast<__nv_bfloat162*>(&Clb[(size_t)(rr + 8) * N + cc]) =
                    __nv_bfloat162(l2, l3);
            }
        }
    }
}

// ---------------------------------------------------------------------------
// transpose + split: [DIM][NTOK] f32 -> [NTOK][DIM] hi/lo bf16, batched
// ---------------------------------------------------------------------------
__global__ __launch_bounds__(256) void k_splitT(const float* __restrict__ in,
                                                bf16* __restrict__ oh,
                                                bf16* __restrict__ ol)
{
    __shared__ float t[32][33];
    const float* ib = in + (size_t)blockIdx.z * DIM * NTOK;
    bf16* ohb = oh + (size_t)blockIdx.z * NTOK * DIM;
    bf16* olb = ol + (size_t)blockIdx.z * NTOK * DIM;
    const int n0 = blockIdx.x * 32, c0 = blockIdx.y * 32;
    const int tx = threadIdx.x & 31, ty = threadIdx.x >> 5;
#pragma unroll
    for (int j = 0; j < 4; j++)
        t[ty + 8 * j][tx] = ib[(size_t)(c0 + ty + 8 * j) * NTOK + n0 + tx];
    __syncthreads();
#pragma unroll
    for (int j = 0; j < 4; j++) {
        float x = t[tx][ty + 8 * j];
        bf16 h, l;
        split1(x, h, l);
        size_t idx = (size_t)(n0 + ty + 8 * j) * DIM + c0 + tx;
        ohb[idx] = h;
        olb[idx] = l;
    }
}

// fused elementwise split for all 4 weights; blockIdx.y selects the weight
__global__ __launch_bounds__(256) void k_splitW4(
    const float* __restrict__ w0, const float* __restrict__ w1,
    const float* __restrict__ w2, const float* __restrict__ w3,
    bf16* __restrict__ oh, bf16* __restrict__ ol)
{
    const float* w = (blockIdx.y == 0) ? w0 : (blockIdx.y == 1) ? w1
                    : (blockIdx.y == 2) ? w2 : w3;
    bf16* ohb = oh + (size_t)blockIdx.y * WW;
    bf16* olb = ol + (size_t)blockIdx.y * WW;
    int i = blockIdx.x * 256 + threadIdx.x;
    float4 v = reinterpret_cast<const float4*>(w)[i];
    bf16 h0, l0, h1, l1, h2, l2, h3, l3;
    split1(v.x, h0, l0); split1(v.y, h1, l1);
    split1(v.z, h2, l2); split1(v.w, h3, l3);
    reinterpret_cast<__nv_bfloat162*>(ohb)[2 * i]     = __nv_bfloat162(h0, h1);
    reinterpret_cast<__nv_bfloat162*>(ohb)[2 * i + 1] = __nv_bfloat162(h2, h3);
    reinterpret_cast<__nv_bfloat162*>(olb)[2 * i]     = __nv_bfloat162(l0, l1);
    reinterpret_cast<__nv_bfloat162*>(olb)[2 * i + 1] = __nv_bfloat162(l2, l3);
}

// ---------------------------------------------------------------------------
// Row softmax: f32 in, split bf16 out. One CTA per row of 1024.
// ---------------------------------------------------------------------------
__global__ __launch_bounds__(256) void k_softmax(const float* __restrict__ S,
                                                 bf16* __restrict__ Ph,
                                                 bf16* __restrict__ Pl)
{
    const float* row = S + (size_t)blockIdx.x * NTOK;
    const int tid = threadIdx.x;
    __shared__ float red[8];

    float4 v = reinterpret_cast<const float4*>(row)[tid];
    float m = fmaxf(fmaxf(v.x, v.y), fmaxf(v.z, v.w));
#pragma unroll
    for (int o = 16; o > 0; o >>= 1)
        m = fmaxf(m, __shfl_xor_sync(0xffffffffu, m, o));
    if ((tid & 31) == 0) red[tid >> 5] = m;
    __syncthreads();
    float mall = fmaxf(fmaxf(red[0], red[1]), fmaxf(red[2], red[3]));
    mall = fmaxf(mall, fmaxf(fmaxf(red[4], red[5]), fmaxf(red[6], red[7])));

    float4 e;
    e.x = expf(v.x - mall);
    e.y = expf(v.y - mall);
    e.z = expf(v.z - mall);
    e.w = expf(v.w - mall);
    float s = e.x + e.y + e.z + e.w;
#pragma unroll
    for (int o = 16; o > 0; o >>= 1)
        s += __shfl_xor_sync(0xffffffffu, s, o);
    __syncthreads();
    if ((tid & 31) == 0) red[tid >> 5] = s;
    __syncthreads();
    float sall = red[0] + red[1] + red[2] + red[3] + red[4] + red[5] + red[6] + red[7];
    float inv = 1.0f / sall;
    e.x *= inv; e.y *= inv; e.z *= inv; e.w *= inv;

    bf16 h0, l0, h1, l1, h2, l2, h3, l3;
    split1(e.x, h0, l0); split1(e.y, h1, l1);
    split1(e.z, h2, l2); split1(e.w, h3, l3);
    bf16* ph = Ph + (size_t)blockIdx.x * NTOK + 4 * tid;
    bf16* pl = Pl + (size_t)blockIdx.x * NTOK + 4 * tid;
    reinterpret_cast<__nv_bfloat162*>(ph)[0] = __nv_bfloat162(h0, h1);
    reinterpret_cast<__nv_bfloat162*>(ph)[1] = __nv_bfloat162(h2, h3);
    reinterpret_cast<__nv_bfloat162*>(pl)[0] = __nv_bfloat162(l0, l1);
    reinterpret_cast<__nv_bfloat162*>(pl)[1] = __nv_bfloat162(l2, l3);
}

// ---------------------------------------------------------------------------
extern "C" void kernel_launch(void* const* d_in, const int* in_sizes, int n_in,
                              void* d_out, int out_size)
{
    const float* rgb = (const float*)d_in[0];
    const float* ms  = (const float*)d_in[1];
    const float* Wq  = (const float*)d_in[2];
    const float* bq  = (const float*)d_in[3];
    const float* Wk  = (const float*)d_in[4];
    const float* bk  = (const float*)d_in[5];
    const float* Wv  = (const float*)d_in[6];
    const float* bv  = (const float*)d_in[7];
    const float* Wf  = (const float*)d_in[8];
    const float* bf_ = (const float*)d_in[9];
    float* out = (float*)d_out;

    bf16 *t1h, *t1l, *t2h, *t2l, *qh, *ql, *kh, *kl, *vh, *vl, *oh, *ol, *Ph, *Pl, *wh, *wl;
    float* s;
    cudaGetSymbolAddress((void**)&t1h, g_t1h); cudaGetSymbolAddress((void**)&t1l, g_t1l);
    cudaGetSymbolAddress((void**)&t2h, g_t2h); cudaGetSymbolAddress((void**)&t2l, g_t2l);
    cudaGetSymbolAddress((void**)&qh,  g_qh);  cudaGetSymbolAddress((void**)&ql,  g_ql);
    cudaGetSymbolAddress((void**)&kh,  g_kh);  cudaGetSymbolAddress((void**)&kl,  g_kl);
    cudaGetSymbolAddress((void**)&vh,  g_vh);  cudaGetSymbolAddress((void**)&vl,  g_vl);
    cudaGetSymbolAddress((void**)&oh,  g_oh);  cudaGetSymbolAddress((void**)&ol,  g_ol);
    cudaGetSymbolAddress((void**)&Ph,  g_Ph);  cudaGetSymbolAddress((void**)&Pl,  g_Pl);
    cudaGetSymbolAddress((void**)&wh,  g_wh);  cudaGetSymbolAddress((void**)&wl,  g_wl);
    cudaGetSymbolAddress((void**)&s,   g_s);

    bf16 *wqh = wh,          *wql = wl;
    bf16 *wkh = wh + WW,     *wkl = wl + WW;
    bf16 *wvh = wh + 2 * WW, *wvl = wl + 2 * WW;
    bf16 *wfh = wh + 3 * WW, *wfl = wl + 3 * WW;

    const float scale = 1.0f / sqrtf((float)DIM);
    const size_t nd = (size_t)NTOK * DIM;
    const size_t nn = (size_t)NTOK * NTOK;

    cudaFuncSetAttribute(k_gemm<0, 0>, cudaFuncAttributeMaxDynamicSharedMemorySize, SMEM_BYTES);
    cudaFuncSetAttribute(k_gemm<0, 1>, cudaFuncAttributeMaxDynamicSharedMemorySize, SMEM_BYTES);
    cudaFuncSetAttribute(k_gemm<1, 0>, cudaFuncAttributeMaxDynamicSharedMemorySize, SMEM_BYTES);
    cudaFuncSetAttribute(k_gemm<1, 1>, cudaFuncAttributeMaxDynamicSharedMemorySize, SMEM_BYTES);
    cudaFuncSetAttribute(k_gemm<1, 2>, cudaFuncAttributeMaxDynamicSharedMemorySize, SMEM_BYTES);

    dim3 blk(256);
    dim3 gT(NTOK / 32, DIM / 32, BATCH);
    dim3 gW((unsigned)(WW / (256 * 4)), 4, 1);

    // Launch order chosen so ncu's "-s 5" lands on the scores GEMM (launch #5).
    k_splitW4<<<gW, blk>>>(Wq, Wk, Wv, Wf, wh, wl);           // 0
    k_splitT<<<gT, blk>>>(rgb, t1h, t1l);                      // 1
    k_splitT<<<gT, blk>>>(ms,  t2h, t2l);                      // 2

    dim3 gQ(DIM / 128, NTOK / 128, BATCH);   // (3, 8, 32)
    dim3 gV(NTOK / 128, DIM / 128, BATCH);   // (8, 3, 32)
    dim3 gS(NTOK / 128, NTOK / 128, BATCH);  // (8, 8, 32)

    // qT[n][d] = t1[n][c] . Wq[d][c] + bq[d]  (col bias, split out)
    k_gemm<1, 2><<<gQ, blk, SMEM_BYTES>>>(t1h, t1l, wqh, wql, bq, nullptr, qh, ql,
                                          NTOK, DIM, DIM, nd, 0, nd, 1.0f);     // 3
    k_gemm<1, 2><<<gQ, blk, SMEM_BYTES>>>(t2h, t2l, wkh, wkl, bk, nullptr, kh, kl,
                                          NTOK, DIM, DIM, nd, 0, nd, 1.0f);     // 4
    // S[i][j] = scale * qT[i][:] . kT[j][:]  (f32 out)  -- launch #5 for ncu
    k_gemm<0, 0><<<gS, blk, SMEM_BYTES>>>(qh, ql, kh, kl, nullptr, s, nullptr, nullptr,
                                          NTOK, NTOK, DIM, nd, nd, nn, scale);  // 5
    // v[d][n] = Wv[d][c] . t2[n][c] + bv[d]  (row bias, split out)
    k_gemm<1, 1><<<gV, blk, SMEM_BYTES>>>(wvh, wvl, t2h, t2l, bv, nullptr, vh, vl,
                                          DIM, NTOK, DIM, 0, nd, nd, 1.0f);     // 6

    k_softmax<<<BATCH * NTOK, 256>>>(s, Ph, Pl);                                // 7

    // oT[n][d] = P[n][m] . v[d][m]  (split out)
    k_gemm<1, 0><<<gQ, blk, SMEM_BYTES>>>(Ph, Pl, vh, vl, nullptr, nullptr, oh, ol,
                                          NTOK, DIM, NTOK, nn, nd, nd, 1.0f);   // 8
    // out[d][n] = Wf[d][c] . oT[n][c] + bf[d]  (f32 out, row bias)
    k_gemm<0, 1><<<gV, blk, SMEM_BYTES>>>(wfh, wfl, oh, ol, bf_, out, nullptr, nullptr,
                                          DIM, NTOK, DIM, 0, nd, nd, 1.0f);     // 9
}

// round 12
// speedup vs baseline: 1.1174x; 1.1174x over previous
#include <cuda_runtime.h>
#include <cuda_bf16.h>
#include <math.h>
#include <stdint.h>

#define BATCH 32
#define DIM   384
#define NTOK  1024
#define STAGES 4

typedef __nv_bfloat16 bf16;

// ---------------------------------------------------------------------------
// Scratch (allocation-free rule: __device__ globals). All operands pre-split
// into hi/lo bf16 pairs; S kept in f32 for softmax precision.
// ---------------------------------------------------------------------------
#define ND ((size_t)BATCH * NTOK * DIM)
#define NN ((size_t)BATCH * NTOK * NTOK)
#define WW ((size_t)DIM * DIM)

__device__ bf16 g_t1h[ND], g_t1l[ND];   // rgb^T [n][c]
__device__ bf16 g_t2h[ND], g_t2l[ND];   // ms^T  [n][c]
__device__ bf16 g_qh[ND],  g_ql[ND];    // qT [n][d]
__device__ bf16 g_kh[ND],  g_kl[ND];    // kT [n][d]
__device__ bf16 g_vh[ND],  g_vl[ND];    // v  [d][n]
__device__ bf16 g_oh[ND],  g_ol[ND];    // oT [n][d]
__device__ bf16 g_Ph[NN],  g_Pl[NN];    // attn [i][m]
__device__ float g_s[NN];               // scores f32
__device__ bf16 g_wh[4 * WW], g_wl[4 * WW]; // Wq,Wk,Wv,Wf split

// ---------------------------------------------------------------------------
// helpers
// ---------------------------------------------------------------------------
__device__ __forceinline__ void split1(float x, bf16& h, bf16& l) {
    h = __float2bfloat16(x);
    l = __float2bfloat16(x - __bfloat162float(h));
}

__device__ __forceinline__ void cpasync16(uint32_t dst, const void* src) {
    asm volatile("cp.async.cg.shared.global [%0], [%1], 16;" :: "r"(dst), "l"(src));
}

__device__ __forceinline__ void ldmA(uint32_t f[4], const uint32_t* base, int rb, int lane) {
    int t = lane >> 3, rr = lane & 7;
    int row = rb + rr + (t & 1) * 8;
    int c = ((t >> 1) << 2) ^ (row & 4);
    uint32_t sa = (uint32_t)__cvta_generic_to_shared(&base[row * 8 + c]);
    asm volatile("ldmatrix.sync.aligned.m8n8.x4.shared.b16 {%0,%1,%2,%3}, [%4];"
                 : "=r"(f[0]), "=r"(f[1]), "=r"(f[2]), "=r"(f[3]) : "r"(sa));
}

__device__ __forceinline__ void ldmB(uint32_t f[2], const uint32_t* base, int cb, int lane) {
    int row = cb + (lane & 7);
    int c = (((lane >> 3) & 1) << 2) ^ (row & 4);
    uint32_t sa = (uint32_t)__cvta_generic_to_shared(&base[row * 8 + c]);
    asm volatile("ldmatrix.sync.aligned.m8n8.x2.shared.b16 {%0,%1}, [%2];"
                 : "=r"(f[0]), "=r"(f[1]) : "r"(sa));
}

__device__ __forceinline__ void mma(float acc[4], const uint32_t a[4], const uint32_t b[2]) {
    asm volatile("mma.sync.aligned.m16n8k16.row.col.f32.bf16.bf16.f32 "
                 "{%0,%1,%2,%3}, {%4,%5,%6,%7}, {%8,%9}, {%0,%1,%2,%3};"
                 : "+f"(acc[0]), "+f"(acc[1]), "+f"(acc[2]), "+f"(acc[3])
                 : "r"(a[0]), "r"(a[1]), "r"(a[2]), "r"(a[3]), "r"(b[0]), "r"(b[1]));
}

// Stage layout (dynamic smem): stage(16KB) = [tile(4: Ah,Al,Bh,Bl)][128 x 8 u32]
#define TILE_U32   1024u
#define STAGE_U32  (4u * TILE_U32)
#define SMEM_BYTES (STAGES * STAGE_U32 * 4u)   // 64KB

// ---------------------------------------------------------------------------
// GEMM body. C[b][m][n] = scale * sum_k (Ah+Al)[m][k]*(Bh+Bl)[n][k] (+bias)
// ---------------------------------------------------------------------------
template<int OUT, int BM>
__device__ __forceinline__ void gemm_body(
    const bf16* __restrict__ Ah, const bf16* __restrict__ Al,
    const bf16* __restrict__ Bh, const bf16* __restrict__ Bl,
    const float* __restrict__ bias,
    float* __restrict__ Cf, bf16* __restrict__ Ch, bf16* __restrict__ Cl,
    int M, int N, int K, size_t strA, size_t strB, size_t strC,
    float scale, size_t zb)
{
    extern __shared__ uint32_t sm[];

    const int tid = threadIdx.x, lane = tid & 31, wid = tid >> 5;
    const int wm = wid >> 2, wn = wid & 3, g = lane >> 2, q = lane & 3;
    const int m0 = blockIdx.y * 128, n0 = blockIdx.x * 128;

    const int r = tid >> 1, h = tid & 1;
    const bf16* pAh = Ah + zb * strA + (size_t)(m0 + r) * K + 8 * h;
    const bf16* pAl = Al + zb * strA + (size_t)(m0 + r) * K + 8 * h;
    const bf16* pBh = Bh + zb * strB + (size_t)(n0 + r) * K + 8 * h;
    const bf16* pBl = Bl + zb * strB + (size_t)(n0 + r) * K + 8 * h;
    const uint32_t dOff = (uint32_t)((r * 8 + ((4 * h) ^ (r & 4))) * 4);
    const uint32_t smBase = (uint32_t)__cvta_generic_to_shared(sm);

    const int nIt = K >> 4;   // TK = 16

    auto issue = [&](int s) {
        if (s < nIt) {
            const size_t ko = (size_t)s * 16;
            const uint32_t sbase = smBase + (uint32_t)(s % STAGES) * (STAGE_U32 * 4u) + dOff;
            cpasync16(sbase + 0 * (TILE_U32 * 4u), pAh + ko);
            cpasync16(sbase + 1 * (TILE_U32 * 4u), pAl + ko);
            cpasync16(sbase + 2 * (TILE_U32 * 4u), pBh + ko);
            cpasync16(sbase + 3 * (TILE_U32 * 4u), pBl + ko);
        }
        asm volatile("cp.async.commit_group;");
    };

    float acc[4][4][4] = {};

    issue(0);
    issue(1);
    issue(2);

    for (int it = 0; it < nIt; it++) {
        asm volatile("cp.async.wait_group 2;");
        __syncthreads();
        issue(it + 3);

        const uint32_t* SAh = sm + (uint32_t)(it % STAGES) * STAGE_U32;
        const uint32_t* SAl = SAh + TILE_U32;
        const uint32_t* SBh = SAh + 2 * TILE_U32;
        const uint32_t* SBl = SAh + 3 * TILE_U32;

        uint32_t bh[4][2], bl[4][2];
#pragma unroll
        for (int nt = 0; nt < 4; nt++) {
            ldmB(bh[nt], SBh, wn * 32 + nt * 8, lane);
            ldmB(bl[nt], SBl, wn * 32 + nt * 8, lane);
        }

#pragma unroll
        for (int mh = 0; mh < 2; mh++) {
            uint32_t ah[2][4], al[2][4];
#pragma unroll
            for (int m2 = 0; m2 < 2; m2++) {
                ldmA(ah[m2], SAh, wm * 64 + (mh * 2 + m2) * 16, lane);
                ldmA(al[m2], SAl, wm * 64 + (mh * 2 + m2) * 16, lane);
            }
#pragma unroll
            for (int m2 = 0; m2 < 2; m2++)
#pragma unroll
                for (int nt = 0; nt < 4; nt++)
                    mma(acc[mh * 2 + m2][nt], ah[m2], bl[nt]);
#pragma unroll
            for (int m2 = 0; m2 < 2; m2++)
#pragma unroll
                for (int nt = 0; nt < 4; nt++)
                    mma(acc[mh * 2 + m2][nt], al[m2], bh[nt]);
#pragma unroll
            for (int m2 = 0; m2 < 2; m2++)
#pragma unroll
                for (int nt = 0; nt < 4; nt++)
                    mma(acc[mh * 2 + m2][nt], ah[m2], bh[nt]);
        }
    }

    float* Cfb = (OUT == 0) ? Cf + zb * strC : nullptr;
    bf16* Chb = (OUT == 1) ? Ch + zb * strC : nullptr;
    bf16* Clb = (OUT == 1) ? Cl + zb * strC : nullptr;

#pragma unroll
    for (int mt = 0; mt < 4; mt++) {
        const int rr = m0 + wm * 64 + mt * 16 + g;
        float br0 = 0.f, br1 = 0.f;
        if (BM == 1) { br0 = bias[rr]; br1 = bias[rr + 8]; }
#pragma unroll
        for (int nt = 0; nt < 4; nt++) {
            const int cc = n0 + wn * 32 + nt * 8 + 2 * q;
            float v0 = acc[mt][nt][0] * scale, v1 = acc[mt][nt][1] * scale;
            float v2 = acc[mt][nt][2] * scale, v3 = acc[mt][nt][3] * scale;
            if (BM == 1) { v0 += br0; v1 += br0; v2 += br1; v3 += br1; }
            if (BM == 2) {
                float bc0 = bias[cc], bc1 = bias[cc + 1];
                v0 += bc0; v1 += bc1; v2 += bc0; v3 += bc1;
            }
            if (OUT == 0) {
                *reinterpret_cast<float2*>(&Cfb[(size_t)rr * N + cc]) = make_float2(v0, v1);
                *reinterpret_cast<float2*>(&Cfb[(size_t)(rr + 8) * N + cc]) = make_float2(v2, v3);
            } else {
                bf16 h0, l0, h1, l1, h2, l2, h3, l3;
                split1(v0, h0, l0); split1(v1, h1, l1);
                split1(v2, h2, l2); split1(v3, h3, l3);
                *reinterpret_cast<__nv_bfloat162*>(&Chb[(size_t)rr * N + cc]) =
                    __nv_bfloat162(h0, h1);
                *reinterpret_cast<__nv_bfloat162*>(&Clb[(size_t)rr * N + cc]) =
                    __nv_bfloat162(l0, l1);
                *reinterpret_cast<__nv_bfloat162*>(&Chb[(size_t)(rr + 8) * N + cc]) =
                    __nv_bfloat162(h2, h3);
                *reinterpret_cast<__nv_bfloat162*>(&Clb[(size_t)(rr + 8) * N + cc]) =
                    __nv_bfloat162(l2, l3);
            }
        }
    }
}

template<int OUT, int BM>
__global__ __launch_bounds__(256, 2) void k_gemm(
    const bf16* __restrict__ Ah, const bf16* __restrict__ Al,
    const bf16* __restrict__ Bh, const bf16* __restrict__ Bl,
    const float* __restrict__ bias,
    float* __restrict__ Cf, bf16* __restrict__ Ch, bf16* __restrict__ Cl,
    int M, int N, int K, size_t strA, size_t strB, size_t strC, float scale)
{
    gemm_body<OUT, BM>(Ah, Al, Bh, Bl, bias, Cf, Ch, Cl,
                       M, N, K, strA, strB, strC, scale, blockIdx.z);
}

// Merged Q+K projection: z in [0,64). z<32 -> Q (t1 x Wq), else K (t2 x Wk).
__global__ __launch_bounds__(256, 2) void k_gemm_qk(
    const bf16* __restrict__ A1h, const bf16* __restrict__ A1l,
    const bf16* __restrict__ A2h, const bf16* __restrict__ A2l,
    const bf16* __restrict__ Wqh, const bf16* __restrict__ Wql,
    const bf16* __restrict__ Wkh, const bf16* __restrict__ Wkl,
    const float* __restrict__ bq, const float* __restrict__ bk,
    bf16* __restrict__ Qh, bf16* __restrict__ Ql,
    bf16* __restrict__ Kh, bf16* __restrict__ Kl,
    size_t strA, size_t strC)
{
    const int sel = blockIdx.z >> 5;
    const size_t zb = blockIdx.z & 31;
    gemm_body<1, 2>(sel ? A2h : A1h, sel ? A2l : A1l,
                    sel ? Wkh : Wqh, sel ? Wkl : Wql,
                    sel ? bk : bq, nullptr,
                    sel ? Kh : Qh, sel ? Kl : Ql,
                    NTOK, DIM, DIM, strA, 0, strC, 1.0f, zb);
}

// ---------------------------------------------------------------------------
// transpose + split: [DIM][NTOK] f32 -> [NTOK][DIM] hi/lo bf16, batched
// ---------------------------------------------------------------------------
__global__ __launch_bounds__(256) void k_splitT(const float* __restrict__ in,
                                                bf16* __restrict__ oh,
                                                bf16* __restrict__ ol)
{
    __shared__ float t[32][33];
    const float* ib = in + (size_t)blockIdx.z * DIM * NTOK;
    bf16* ohb = oh + (size_t)blockIdx.z * NTOK * DIM;
    bf16* olb = ol + (size_t)blockIdx.z * NTOK * DIM;
    const int n0 = blockIdx.x * 32, c0 = blockIdx.y * 32;
    const int tx = threadIdx.x & 31, ty = threadIdx.x >> 5;
#pragma unroll
    for (int j = 0; j < 4; j++)
        t[ty + 8 * j][tx] = ib[(size_t)(c0 + ty + 8 * j) * NTOK + n0 + tx];
    __syncthreads();
#pragma unroll
    for (int j = 0; j < 4; j++) {
        float x = t[tx][ty + 8 * j];
        bf16 h, l;
        split1(x, h, l);
        size_t idx = (size_t)(n0 + ty + 8 * j) * DIM + c0 + tx;
        ohb[idx] = h;
        olb[idx] = l;
    }
}

// fused elementwise split for all 4 weights; blockIdx.y selects the weight
__global__ __launch_bounds__(256) void k_splitW4(
    const float* __restrict__ w0, const float* __restrict__ w1,
    const float* __restrict__ w2, const float* __restrict__ w3,
    bf16* __restrict__ oh, bf16* __restrict__ ol)
{
    const float* w = (blockIdx.y == 0) ? w0 : (blockIdx.y == 1) ? w1
                    : (blockIdx.y == 2) ? w2 : w3;
    bf16* ohb = oh + (size_t)blockIdx.y * WW;
    bf16* olb = ol + (size_t)blockIdx.y * WW;
    int i = blockIdx.x * 256 + threadIdx.x;
    float4 v = reinterpret_cast<const float4*>(w)[i];
    bf16 h0, l0, h1, l1, h2, l2, h3, l3;
    split1(v.x, h0, l0); split1(v.y, h1, l1);
    split1(v.z, h2, l2); split1(v.w, h3, l3);
    reinterpret_cast<__nv_bfloat162*>(ohb)[2 * i]     = __nv_bfloat162(h0, h1);
    reinterpret_cast<__nv_bfloat162*>(ohb)[2 * i + 1] = __nv_bfloat162(h2, h3);
    reinterpret_cast<__nv_bfloat162*>(olb)[2 * i]     = __nv_bfloat162(l0, l1);
    reinterpret_cast<__nv_bfloat162*>(olb)[2 * i + 1] = __nv_bfloat162(l2, l3);
}

// ---------------------------------------------------------------------------
// Row softmax: f32 in, split bf16 out. One CTA per row of 1024.
// ---------------------------------------------------------------------------
__global__ __launch_bounds__(256) void k_softmax(const float* __restrict__ S,
                                                 bf16* __restrict__ Ph,
                                                 bf16* __restrict__ Pl)
{
    const float* row = S + (size_t)blockIdx.x * NTOK;
    const int tid = threadIdx.x;
    __shared__ float red[8];

    float4 v = reinterpret_cast<const float4*>(row)[tid];
    float m = fmaxf(fmaxf(v.x, v.y), fmaxf(v.z, v.w));
#pragma unroll
    for (int o = 16; o > 0; o >>= 1)
        m = fmaxf(m, __shfl_xor_sync(0xffffffffu, m, o));
    if ((tid & 31) == 0) red[tid >> 5] = m;
    __syncthreads();
    float mall = fmaxf(fmaxf(red[0], red[1]), fmaxf(red[2], red[3]));
    mall = fmaxf(mall, fmaxf(fmaxf(red[4], red[5]), fmaxf(red[6], red[7])));

    float4 e;
    e.x = expf(v.x - mall);
    e.y = expf(v.y - mall);
    e.z = expf(v.z - mall);
    e.w = expf(v.w - mall);
    float s = e.x + e.y + e.z + e.w;
#pragma unroll
    for (int o = 16; o > 0; o >>= 1)
        s += __shfl_xor_sync(0xffffffffu, s, o);
    __syncthreads();
    if ((tid & 31) == 0) red[tid >> 5] = s;
    __syncthreads();
    float sall = red[0] + red[1] + red[2] + red[3] + red[4] + red[5] + red[6] + red[7];
    float inv = 1.0f / sall;
    e.x *= inv; e.y *= inv; e.z *= inv; e.w *= inv;

    bf16 h0, l0, h1, l1, h2, l2, h3, l3;
    split1(e.x, h0, l0); split1(e.y, h1, l1);
    split1(e.z, h2, l2); split1(e.w, h3, l3);
    bf16* ph = Ph + (size_t)blockIdx.x * NTOK + 4 * tid;
    bf16* pl = Pl + (size_t)blockIdx.x * NTOK + 4 * tid;
    reinterpret_cast<__nv_bfloat162*>(ph)[0] = __nv_bfloat162(h0, h1);
    reinterpret_cast<__nv_bfloat162*>(ph)[1] = __nv_bfloat162(h2, h3);
    reinterpret_cast<__nv_bfloat162*>(pl)[0] = __nv_bfloat162(l0, l1);
    reinterpret_cast<__nv_bfloat162*>(pl)[1] = __nv_bfloat162(l2, l3);
}

// ---------------------------------------------------------------------------
extern "C" void kernel_launch(void* const* d_in, const int* in_sizes, int n_in,
                              void* d_out, int out_size)
{
    const float* rgb = (const float*)d_in[0];
    const float* ms  = (const float*)d_in[1];
    const float* Wq  = (const float*)d_in[2];
    const float* bq  = (const float*)d_in[3];
    const float* Wk  = (const float*)d_in[4];
    const float* bk  = (const float*)d_in[5];
    const float* Wv  = (const float*)d_in[6];
    const float* bv  = (const float*)d_in[7];
    const float* Wf  = (const float*)d_in[8];
    const float* bf_ = (const float*)d_in[9];
    float* out = (float*)d_out;

    bf16 *t1h, *t1l, *t2h, *t2l, *qh, *ql, *kh, *kl, *vh, *vl, *oh, *ol, *Ph, *Pl, *wh, *wl;
    float* s;
    cudaGetSymbolAddress((void**)&t1h, g_t1h); cudaGetSymbolAddress((void**)&t1l, g_t1l);
    cudaGetSymbolAddress((void**)&t2h, g_t2h); cudaGetSymbolAddress((void**)&t2l, g_t2l);
    cudaGetSymbolAddress((void**)&qh,  g_qh);  cudaGetSymbolAddress((void**)&ql,  g_ql);
    cudaGetSymbolAddress((void**)&kh,  g_kh);  cudaGetSymbolAddress((void**)&kl,  g_kl);
    cudaGetSymbolAddress((void**)&vh,  g_vh);  cudaGetSymbolAddress((void**)&vl,  g_vl);
    cudaGetSymbolAddress((void**)&oh,  g_oh);  cudaGetSymbolAddress((void**)&ol,  g_ol);
    cudaGetSymbolAddress((void**)&Ph,  g_Ph);  cudaGetSymbolAddress((void**)&Pl,  g_Pl);
    cudaGetSymbolAddress((void**)&wh,  g_wh);  cudaGetSymbolAddress((void**)&wl,  g_wl);
    cudaGetSymbolAddress((void**)&s,   g_s);

    bf16 *wqh = wh,          *wql = wl;
    bf16 *wkh = wh + WW,     *wkl = wl + WW;
    bf16 *wvh = wh + 2 * WW, *wvl = wl + 2 * WW;
    bf16 *wfh = wh + 3 * WW, *wfl = wl + 3 * WW;

    const float scale = 1.0f / sqrtf((float)DIM);
    const size_t nd = (size_t)NTOK * DIM;
    const size_t nn = (size_t)NTOK * NTOK;

    cudaFuncSetAttribute(k_gemm<0, 0>, cudaFuncAttributeMaxDynamicSharedMemorySize, SMEM_BYTES);
    cudaFuncSetAttribute(k_gemm<0, 1>, cudaFuncAttributeMaxDynamicSharedMemorySize, SMEM_BYTES);
    cudaFuncSetAttribute(k_gemm<1, 0>, cudaFuncAttributeMaxDynamicSharedMemorySize, SMEM_BYTES);
    cudaFuncSetAttribute(k_gemm<1, 1>, cudaFuncAttributeMaxDynamicSharedMemorySize, SMEM_BYTES);
    cudaFuncSetAttribute(k_gemm_qk,    cudaFuncAttributeMaxDynamicSharedMemorySize, SMEM_BYTES);

    dim3 blk(256);
    dim3 gT(NTOK / 32, DIM / 32, BATCH);
    dim3 gW((unsigned)(WW / (256 * 4)), 4, 1);

    // Launch order: ncu "-s 5" lands on the scores GEMM (launch #5).
    k_splitW4<<<gW, blk>>>(Wq, Wk, Wv, Wf, wh, wl);            // 0
    k_splitT<<<gT, blk>>>(rgb, t1h, t1l);                       // 1
    k_splitT<<<gT, blk>>>(ms,  t2h, t2l);                       // 2

    dim3 gQK(DIM / 128, NTOK / 128, 2 * BATCH);  // (3, 8, 64)
    dim3 gQ(DIM / 128, NTOK / 128, BATCH);       // (3, 8, 32)
    dim3 gV(NTOK / 128, DIM / 128, BATCH);       // (8, 3, 32)
    dim3 gS(NTOK / 128, NTOK / 128, BATCH);      // (8, 8, 32)

    // q/k projections merged                                    // 3
    k_gemm_qk<<<gQK, blk, SMEM_BYTES>>>(t1h, t1l, t2h, t2l,
                                        wqh, wql, wkh, wkl, bq, bk,
                                        qh, ql, kh, kl, nd, nd);
    // v[d][n] = Wv[d][c] . t2[n][c] + bv[d]                     // 4
    k_gemm<1, 1><<<gV, blk, SMEM_BYTES>>>(wvh, wvl, t2h, t2l, bv, nullptr, vh, vl,
                                          DIM, NTOK, DIM, 0, nd, nd, 1.0f);
    // S[i][j] = scale * qT[i][:] . kT[j][:]                     // 5  (ncu target)
    k_gemm<0, 0><<<gS, blk, SMEM_BYTES>>>(qh, ql, kh, kl, nullptr, s, nullptr, nullptr,
                                          NTOK, NTOK, DIM, nd, nd, nn, scale);

    k_softmax<<<BATCH * NTOK, 256>>>(s, Ph, Pl);                 // 6

    // oT[n][d] = P[n][m] . v[d][m]                              // 7
    k_gemm<1, 0><<<gQ, blk, SMEM_BYTES>>>(Ph, Pl, vh, vl, nullptr, nullptr, oh, ol,
                                          NTOK, DIM, NTOK, nn, nd, nd, 1.0f);
    // out[d][n] = Wf[d][c] . oT[n][c] + bf[d]                   // 8
    k_gemm<0, 1><<<gV, blk, SMEM_BYTES>>>(wfh, wfl, oh, ol, bf_, out, nullptr, nullptr,
                                          DIM, NTOK, DIM, 0, nd, nd, 1.0f);
}

// round 14
// speedup vs baseline: 1.2180x; 1.0901x over previous
#include <cuda_runtime.h>
#include <cuda_bf16.h>
#include <math.h>
#include <stdint.h>

#define BATCH 32
#define DIM   384
#define NTOK  1024
#define STAGES 6

typedef __nv_bfloat16 bf16;

// ---------------------------------------------------------------------------
// Scratch (allocation-free rule: __device__ globals). All operands pre-split
// into hi/lo bf16 pairs; S kept in f32 for softmax precision.
// ---------------------------------------------------------------------------
#define ND ((size_t)BATCH * NTOK * DIM)
#define NN ((size_t)BATCH * NTOK * NTOK)
#define WW ((size_t)DIM * DIM)

__device__ bf16 g_t1h[ND], g_t1l[ND];   // rgb^T [n][c]
__device__ bf16 g_t2h[ND], g_t2l[ND];   // ms^T  [n][c]
__device__ bf16 g_qh[ND],  g_ql[ND];    // qT [n][d]
__device__ bf16 g_kh[ND],  g_kl[ND];    // kT [n][d]
__device__ bf16 g_vh[ND],  g_vl[ND];    // v  [d][n]
__device__ bf16 g_oh[ND],  g_ol[ND];    // oT [n][d]
__device__ bf16 g_Ph[NN],  g_Pl[NN];    // attn [i][m]
__device__ float g_s[NN];               // scores f32
__device__ bf16 g_wh[4 * WW], g_wl[4 * WW]; // Wq,Wk,Wv,Wf split

// ---------------------------------------------------------------------------
// helpers
// ---------------------------------------------------------------------------
__device__ __forceinline__ void split1(float x, bf16& h, bf16& l) {
    h = __float2bfloat16(x);
    l = __float2bfloat16(x - __bfloat162float(h));
}

__device__ __forceinline__ void cpasync16(uint32_t dst, const void* src) {
    asm volatile("cp.async.cg.shared.global [%0], [%1], 16;" :: "r"(dst), "l"(src));
}

__device__ __forceinline__ void ldmA(uint32_t f[4], const uint32_t* base, int rb, int lane) {
    int t = lane >> 3, rr = lane & 7;
    int row = rb + rr + (t & 1) * 8;
    int c = ((t >> 1) << 2) ^ (row & 4);
    uint32_t sa = (uint32_t)__cvta_generic_to_shared(&base[row * 8 + c]);
    asm volatile("ldmatrix.sync.aligned.m8n8.x4.shared.b16 {%0,%1,%2,%3}, [%4];"
                 : "=r"(f[0]), "=r"(f[1]), "=r"(f[2]), "=r"(f[3]) : "r"(sa));
}

__device__ __forceinline__ void ldmB(uint32_t f[2], const uint32_t* base, int cb, int lane) {
    int row = cb + (lane & 7);
    int c = (((lane >> 3) & 1) << 2) ^ (row & 4);
    uint32_t sa = (uint32_t)__cvta_generic_to_shared(&base[row * 8 + c]);
    asm volatile("ldmatrix.sync.aligned.m8n8.x2.shared.b16 {%0,%1}, [%2];"
                 : "=r"(f[0]), "=r"(f[1]) : "r"(sa));
}

__device__ __forceinline__ void mma(float acc[4], const uint32_t a[4], const uint32_t b[2]) {
    asm volatile("mma.sync.aligned.m16n8k16.row.col.f32.bf16.bf16.f32 "
                 "{%0,%1,%2,%3}, {%4,%5,%6,%7}, {%8,%9}, {%0,%1,%2,%3};"
                 : "+f"(acc[0]), "+f"(acc[1]), "+f"(acc[2]), "+f"(acc[3])
                 : "r"(a[0]), "r"(a[1]), "r"(a[2]), "r"(a[3]), "r"(b[0]), "r"(b[1]));
}

// Stage layout (dynamic smem): stage(16KB) = [tile(4: Ah,Al,Bh,Bl)][128 x 8 u32]
#define TILE_U32   1024u
#define STAGE_U32  (4u * TILE_U32)
#define SMEM_BYTES (STAGES * STAGE_U32 * 4u)   // 96KB

// ---------------------------------------------------------------------------
// GEMM body. C[b][m][n] = scale * sum_k (Ah+Al)[m][k]*(Bh+Bl)[n][k] (+bias)
// 6-stage cp.async ring; CTA barrier every 2 iterations (write target is
// always 2 logical stages behind the oldest live reader, so skew<=2 is safe).
// ---------------------------------------------------------------------------
template<int OUT, int BM>
__device__ __forceinline__ void gemm_body(
    const bf16* __restrict__ Ah, const bf16* __restrict__ Al,
    const bf16* __restrict__ Bh, const bf16* __restrict__ Bl,
    const float* __restrict__ bias,
    float* __restrict__ Cf, bf16* __restrict__ Ch, bf16* __restrict__ Cl,
    int M, int N, int K, size_t strA, size_t strB, size_t strC,
    float scale, size_t zb)
{
    extern __shared__ uint32_t sm[];

    const int tid = threadIdx.x, lane = tid & 31, wid = tid >> 5;
    const int wm = wid >> 2, wn = wid & 3, g = lane >> 2, q = lane & 3;
    const int m0 = blockIdx.y * 128, n0 = blockIdx.x * 128;

    const int r = tid >> 1, h = tid & 1;
    const bf16* pAh = Ah + zb * strA + (size_t)(m0 + r) * K + 8 * h;
    const bf16* pAl = Al + zb * strA + (size_t)(m0 + r) * K + 8 * h;
    const bf16* pBh = Bh + zb * strB + (size_t)(n0 + r) * K + 8 * h;
    const bf16* pBl = Bl + zb * strB + (size_t)(n0 + r) * K + 8 * h;
    const uint32_t dOff = (uint32_t)((r * 8 + ((4 * h) ^ (r & 4))) * 4);
    const uint32_t smBase = (uint32_t)__cvta_generic_to_shared(sm);

    const int nIt = K >> 4;   // TK = 16

    auto issue = [&](int s) {
        if (s < nIt) {
            const size_t ko = (size_t)s * 16;
            const uint32_t sbase = smBase + (uint32_t)(s % STAGES) * (STAGE_U32 * 4u) + dOff;
            cpasync16(sbase + 0 * (TILE_U32 * 4u), pAh + ko);
            cpasync16(sbase + 1 * (TILE_U32 * 4u), pAl + ko);
            cpasync16(sbase + 2 * (TILE_U32 * 4u), pBh + ko);
            cpasync16(sbase + 3 * (TILE_U32 * 4u), pBl + ko);
        }
        asm volatile("cp.async.commit_group;");
    };

    float acc[4][4][4] = {};

    issue(0);
    issue(1);
    issue(2);
    issue(3);

    for (int it = 0; it < nIt; it++) {
        asm volatile("cp.async.wait_group 3;");
        if ((it & 1) == 0) __syncthreads();

        const uint32_t* SAh = sm + (uint32_t)(it % STAGES) * STAGE_U32;
        const uint32_t* SAl = SAh + TILE_U32;
        const uint32_t* SBh = SAh + 2 * TILE_U32;
        const uint32_t* SBl = SAh + 3 * TILE_U32;

        uint32_t bh[4][2], bl[4][2];
#pragma unroll
        for (int nt = 0; nt < 4; nt++) {
            ldmB(bh[nt], SBh, wn * 32 + nt * 8, lane);
            ldmB(bl[nt], SBl, wn * 32 + nt * 8, lane);
        }

#pragma unroll
        for (int mh = 0; mh < 2; mh++) {
            uint32_t ah[2][4], al[2][4];
#pragma unroll
            for (int m2 = 0; m2 < 2; m2++) {
                ldmA(ah[m2], SAh, wm * 64 + (mh * 2 + m2) * 16, lane);
                ldmA(al[m2], SAl, wm * 64 + (mh * 2 + m2) * 16, lane);
            }
#pragma unroll
            for (int m2 = 0; m2 < 2; m2++)
#pragma unroll
                for (int nt = 0; nt < 4; nt++)
                    mma(acc[mh * 2 + m2][nt], ah[m2], bl[nt]);
#pragma unroll
            for (int m2 = 0; m2 < 2; m2++)
#pragma unroll
                for (int nt = 0; nt < 4; nt++)
                    mma(acc[mh * 2 + m2][nt], al[m2], bh[nt]);
#pragma unroll
            for (int m2 = 0; m2 < 2; m2++)
#pragma unroll
                for (int nt = 0; nt < 4; nt++)
                    mma(acc[mh * 2 + m2][nt], ah[m2], bh[nt]);
        }

        issue(it + 4);
    }

    float* Cfb = (OUT == 0) ? Cf + zb * strC : nullptr;
    bf16* Chb = (OUT == 1) ? Ch + zb * strC : nullptr;
    bf16* Clb = (OUT == 1) ? Cl + zb * strC : nullptr;

#pragma unroll
    for (int mt = 0; mt < 4; mt++) {
        const int rr = m0 + wm * 64 + mt * 16 + g;
        float br0 = 0.f, br1 = 0.f;
        if (BM == 1) { br0 = bias[rr]; br1 = bias[rr + 8]; }
#pragma unroll
        for (int nt = 0; nt < 4; nt++) {
            const int cc = n0 + wn * 32 + nt * 8 + 2 * q;
            float v0 = acc[mt][nt][0] * scale, v1 = acc[mt][nt][1] * scale;
            float v2 = acc[mt][nt][2] * scale, v3 = acc[mt][nt][3] * scale;
            if (BM == 1) { v0 += br0; v1 += br0; v2 += br1; v3 += br1; }
            if (BM == 2) {
                float bc0 = bias[cc], bc1 = bias[cc + 1];
                v0 += bc0; v1 += bc1; v2 += bc0; v3 += bc1;
            }
            if (OUT == 0) {
                *reinterpret_cast<float2*>(&Cfb[(size_t)rr * N + cc]) = make_float2(v0, v1);
                *reinterpret_cast<float2*>(&Cfb[(size_t)(rr + 8) * N + cc]) = make_float2(v2, v3);
            } else {
                bf16 h0, l0, h1, l1, h2, l2, h3, l3;
                split1(v0, h0, l0); split1(v1, h1, l1);
                split1(v2, h2, l2); split1(v3, h3, l3);
                *reinterpret_cast<__nv_bfloat162*>(&Chb[(size_t)rr * N + cc]) =
                    __nv_bfloat162(h0, h1);
                *reinterpret_cast<__nv_bfloat162*>(&Clb[(size_t)rr * N + cc]) =
                    __nv_bfloat162(l0, l1);
                *reinterpret_cast<__nv_bfloat162*>(&Chb[(size_t)(rr + 8) * N + cc]) =
                    __nv_bfloat162(h2, h3);
                *reinterpret_cast<__nv_bfloat162*>(&Clb[(size_t)(rr + 8) * N + cc]) =
                    __nv_bfloat162(l2, l3);
            }
        }
    }
}

template<int OUT, int BM>
__global__ __launch_bounds__(256, 2) void k_gemm(
    const bf16* __restrict__ Ah, const bf16* __restrict__ Al,
    const bf16* __restrict__ Bh, const bf16* __restrict__ Bl,
    const float* __restrict__ bias,
    float* __restrict__ Cf, bf16* __restrict__ Ch, bf16* __restrict__ Cl,
    int M, int N, int K, size_t strA, size_t strB, size_t strC, float scale)
{
    gemm_body<OUT, BM>(Ah, Al, Bh, Bl, bias, Cf, Ch, Cl,
                       M, N, K, strA, strB, strC, scale, blockIdx.z);
}

// Merged Q+K projection: z in [0,64). z<32 -> Q (t1 x Wq), else K (t2 x Wk).
__global__ __launch_bounds__(256, 2) void k_gemm_qk(
    const bf16* __restrict__ A1h, const bf16* __restrict__ A1l,
    const bf16* __restrict__ A2h, const bf16* __restrict__ A2l,
    const bf16* __restrict__ Wqh, const bf16* __restrict__ Wql,
    const bf16* __restrict__ Wkh, const bf16* __restrict__ Wkl,
    const float* __restrict__ bq, const float* __restrict__ bk,
    bf16* __restrict__ Qh, bf16* __restrict__ Ql,
    bf16* __restrict__ Kh, bf16* __restrict__ Kl,
    size_t strA, size_t strC)
{
    const int sel = blockIdx.z >> 5;
    const size_t zb = blockIdx.z & 31;
    gemm_body<1, 2>(sel ? A2h : A1h, sel ? A2l : A1l,
                    sel ? Wkh : Wqh, sel ? Wkl : Wql,
                    sel ? bk : bq, nullptr,
                    sel ? Kh : Qh, sel ? Kl : Ql,
                    NTOK, DIM, DIM, strA, 0, strC, 1.0f, zb);
}

// ---------------------------------------------------------------------------
// transpose + split: [DIM][NTOK] f32 -> [NTOK][DIM] hi/lo bf16, batched
// ---------------------------------------------------------------------------
__global__ __launch_bounds__(256) void k_splitT(const float* __restrict__ in,
                                                bf16* __restrict__ oh,
                                                bf16* __restrict__ ol)
{
    __shared__ float t[32][33];
    const float* ib = in + (size_t)blockIdx.z * DIM * NTOK;
    bf16* ohb = oh + (size_t)blockIdx.z * NTOK * DIM;
    bf16* olb = ol + (size_t)blockIdx.z * NTOK * DIM;
    const int n0 = blockIdx.x * 32, c0 = blockIdx.y * 32;
    const int tx = threadIdx.x & 31, ty = threadIdx.x >> 5;
#pragma unroll
    for (int j = 0; j < 4; j++)
        t[ty + 8 * j][tx] = ib[(size_t)(c0 + ty + 8 * j) * NTOK + n0 + tx];
    __syncthreads();
#pragma unroll
    for (int j = 0; j < 4; j++) {
        float x = t[tx][ty + 8 * j];
        bf16 h, l;
        split1(x, h, l);
        size_t idx = (size_t)(n0 + ty + 8 * j) * DIM + c0 + tx;
        ohb[idx] = h;
        olb[idx] = l;
    }
}

// fused elementwise split for all 4 weights; blockIdx.y selects the weight
__global__ __launch_bounds__(256) void k_splitW4(
    const float* __restrict__ w0, const float* __restrict__ w1,
    const float* __restrict__ w2, const float* __restrict__ w3,
    bf16* __restrict__ oh, bf16* __restrict__ ol)
{
    const float* w = (blockIdx.y == 0) ? w0 : (blockIdx.y == 1) ? w1
                    : (blockIdx.y == 2) ? w2 : w3;
    bf16* ohb = oh + (size_t)blockIdx.y * WW;
    bf16* olb = ol + (size_t)blockIdx.y * WW;
    int i = blockIdx.x * 256 + threadIdx.x;
    float4 v = reinterpret_cast<const float4*>(w)[i];
    bf16 h0, l0, h1, l1, h2, l2, h3, l3;
    split1(v.x, h0, l0); split1(v.y, h1, l1);
    split1(v.z, h2, l2); split1(v.w, h3, l3);
    reinterpret_cast<__nv_bfloat162*>(ohb)[2 * i]     = __nv_bfloat162(h0, h1);
    reinterpret_cast<__nv_bfloat162*>(ohb)[2 * i + 1] = __nv_bfloat162(h2, h3);
    reinterpret_cast<__nv_bfloat162*>(olb)[2 * i]     = __nv_bfloat162(l0, l1);
    reinterpret_cast<__nv_bfloat162*>(olb)[2 * i + 1] = __nv_bfloat162(l2, l3);
}

// ---------------------------------------------------------------------------
// Row softmax: f32 in, split bf16 out. One CTA per row of 1024.
// ---------------------------------------------------------------------------
__global__ __launch_bounds__(256) void k_softmax(const float* __restrict__ S,
                                                 bf16* __restrict__ Ph,
                                                 bf16* __restrict__ Pl)
{
    const float* row = S + (size_t)blockIdx.x * NTOK;
    const int tid = threadIdx.x;
    __shared__ float red[8];

    float4 v = reinterpret_cast<const float4*>(row)[tid];
    float m = fmaxf(fmaxf(v.x, v.y), fmaxf(v.z, v.w));
#pragma unroll
    for (int o = 16; o > 0; o >>= 1)
        m = fmaxf(m, __shfl_xor_sync(0xffffffffu, m, o));
    if ((tid & 31) == 0) red[tid >> 5] = m;
    __syncthreads();
    float mall = fmaxf(fmaxf(red[0], red[1]), fmaxf(red[2], red[3]));
    mall = fmaxf(mall, fmaxf(fmaxf(red[4], red[5]), fmaxf(red[6], red[7])));

    float4 e;
    e.x = expf(v.x - mall);
    e.y = expf(v.y - mall);
    e.z = expf(v.z - mall);
    e.w = expf(v.w - mall);
    float s = e.x + e.y + e.z + e.w;
#pragma unroll
    for (int o = 16; o > 0; o >>= 1)
        s += __shfl_xor_sync(0xffffffffu, s, o);
    __syncthreads();
    if ((tid & 31) == 0) red[tid >> 5] = s;
    __syncthreads();
    float sall = red[0] + red[1] + red[2] + red[3] + red[4] + red[5] + red[6] + red[7];
    float inv = 1.0f / sall;
    e.x *= inv; e.y *= inv; e.z *= inv; e.w *= inv;

    bf16 h0, l0, h1, l1, h2, l2, h3, l3;
    split1(e.x, h0, l0); split1(e.y, h1, l1);
    split1(e.z, h2, l2); split1(e.w, h3, l3);
    bf16* ph = Ph + (size_t)blockIdx.x * NTOK + 4 * tid;
    bf16* pl = Pl + (size_t)blockIdx.x * NTOK + 4 * tid;
    reinterpret_cast<__nv_bfloat162*>(ph)[0] = __nv_bfloat162(h0, h1);
    reinterpret_cast<__nv_bfloat162*>(ph)[1] = __nv_bfloat162(h2, h3);
    reinterpret_cast<__nv_bfloat162*>(pl)[0] = __nv_bfloat162(l0, l1);
    reinterpret_cast<__nv_bfloat162*>(pl)[1] = __nv_bfloat162(l2, l3);
}

// ---------------------------------------------------------------------------
extern "C" void kernel_launch(void* const* d_in, const int* in_sizes, int n_in,
                              void* d_out, int out_size)
{
    const float* rgb = (const float*)d_in[0];
    const float* ms  = (const float*)d_in[1];
    const float* Wq  = (const float*)d_in[2];
    const float* bq  = (const float*)d_in[3];
    const float* Wk  = (const float*)d_in[4];
    const float* bk  = (const float*)d_in[5];
    const float* Wv  = (const float*)d_in[6];
    const float* bv  = (const float*)d_in[7];
    const float* Wf  = (const float*)d_in[8];
    const float* bf_ = (const float*)d_in[9];
    float* out = (float*)d_out;

    bf16 *t1h, *t1l, *t2h, *t2l, *qh, *ql, *kh, *kl, *vh, *vl, *oh, *ol, *Ph, *Pl, *wh, *wl;
    float* s;
    cudaGetSymbolAddress((void**)&t1h, g_t1h); cudaGetSymbolAddress((void**)&t1l, g_t1l);
    cudaGetSymbolAddress((void**)&t2h, g_t2h); cudaGetSymbolAddress((void**)&t2l, g_t2l);
    cudaGetSymbolAddress((void**)&qh,  g_qh);  cudaGetSymbolAddress((void**)&ql,  g_ql);
    cudaGetSymbolAddress((void**)&kh,  g_kh);  cudaGetSymbolAddress((void**)&kl,  g_kl);
    cudaGetSymbolAddress((void**)&vh,  g_vh);  cudaGetSymbolAddress((void**)&vl,  g_vl);
    cudaGetSymbolAddress((void**)&oh,  g_oh);  cudaGetSymbolAddress((void**)&ol,  g_ol);
    cudaGetSymbolAddress((void**)&Ph,  g_Ph);  cudaGetSymbolAddress((void**)&Pl,  g_Pl);
    cudaGetSymbolAddress((void**)&wh,  g_wh);  cudaGetSymbolAddress((void**)&wl,  g_wl);
    cudaGetSymbolAddress((void**)&s,   g_s);

    bf16 *wqh = wh,          *wql = wl;
    bf16 *wkh = wh + WW,     *wkl = wl + WW;
    bf16 *wvh = wh + 2 * WW, *wvl = wl + 2 * WW;
    bf16 *wfh = wh + 3 * WW, *wfl = wl + 3 * WW;

    const float scale = 1.0f / sqrtf((float)DIM);
    const size_t nd = (size_t)NTOK * DIM;
    const size_t nn = (size_t)NTOK * NTOK;

    cudaFuncSetAttribute(k_gemm<0, 0>, cudaFuncAttributeMaxDynamicSharedMemorySize, SMEM_BYTES);
    cudaFuncSetAttribute(k_gemm<0, 1>, cudaFuncAttributeMaxDynamicSharedMemorySize, SMEM_BYTES);
    cudaFuncSetAttribute(k_gemm<1, 0>, cudaFuncAttributeMaxDynamicSharedMemorySize, SMEM_BYTES);
    cudaFuncSetAttribute(k_gemm<1, 1>, cudaFuncAttributeMaxDynamicSharedMemorySize, SMEM_BYTES);
    cudaFuncSetAttribute(k_gemm_qk,    cudaFuncAttributeMaxDynamicSharedMemorySize, SMEM_BYTES);

    dim3 blk(256);
    dim3 gT(NTOK / 32, DIM / 32, BATCH);
    dim3 gW((unsigned)(WW / (256 * 4)), 4, 1);

    // Launch order: ncu "-s 5" lands on the scores GEMM (launch #5).
    k_splitW4<<<gW, blk>>>(Wq, Wk, Wv, Wf, wh, wl);            // 0
    k_splitT<<<gT, blk>>>(rgb, t1h, t1l);                       // 1
    k_splitT<<<gT, blk>>>(ms,  t2h, t2l);                       // 2

    dim3 gQK(DIM / 128, NTOK / 128, 2 * BATCH);  // (3, 8, 64)
    dim3 gQ(DIM / 128, NTOK / 128, BATCH);       // (3, 8, 32)
    dim3 gV(NTOK / 128, DIM / 128, BATCH);       // (8, 3, 32)
    dim3 gS(NTOK / 128, NTOK / 128, BATCH);      // (8, 8, 32)

    // q/k projections merged                                    // 3
    k_gemm_qk<<<gQK, blk, SMEM_BYTES>>>(t1h, t1l, t2h, t2l,
                                        wqh, wql, wkh, wkl, bq, bk,
                                        qh, ql, kh, kl, nd, nd);
    // v[d][n] = Wv[d][c] . t2[n][c] + bv[d]                     // 4
    k_gemm<1, 1><<<gV, blk, SMEM_BYTES>>>(wvh, wvl, t2h, t2l, bv, nullptr, vh, vl,
                                          DIM, NTOK, DIM, 0, nd, nd, 1.0f);
    // S[i][j] = scale * qT[i][:] . kT[j][:]                     // 5  (ncu target)
    k_gemm<0, 0><<<gS, blk, SMEM_BYTES>>>(qh, ql, kh, kl, nullptr, s, nullptr, nullptr,
                                          NTOK, NTOK, DIM, nd, nd, nn, scale);

    k_softmax<<<BATCH * NTOK, 256>>>(s, Ph, Pl);                 // 6

    // oT[n][d] = P[n][m] . v[d][m]                              // 7
    k_gemm<1, 0><<<gQ, blk, SMEM_BYTES>>>(Ph, Pl, vh, vl, nullptr, nullptr, oh, ol,
                                          NTOK, DIM, NTOK, nn, nd, nd, 1.0f);
    // out[d][n] = Wf[d][c] . oT[n][c] + bf[d]                   // 8
    k_gemm<0, 1><<<gV, blk, SMEM_BYTES>>>(wfh, wfl, oh, ol, bf_, out, nullptr, nullptr,
                                          DIM, NTOK, DIM, 0, nd, nd, 1.0f);
}